// round 12
// baseline (speedup 1.0000x reference)
#include <cuda_runtime.h>
#include <cuda_bf16.h>
#include <math.h>
#include <stdint.h>

// Problem constants
#define BB 512
#define NN 128
#define DD 512
#define HH 8
#define DH 64
#define TWO_D 1024
#define STEPS 6

#define SWZ(off) ((off) ^ (((off) >> 3) & 0x70))

// ---------------- PTX helpers (sm_80+ features only) ------------------------
__device__ __forceinline__ void cp_async16(uint32_t smem_addr, const void* gptr) {
    asm volatile("cp.async.cg.shared.global [%0], [%1], 16;\n"
                 :: "r"(smem_addr), "l"(gptr));
}
__device__ __forceinline__ void cp_commit() {
    asm volatile("cp.async.commit_group;\n" ::: "memory");
}
template<int N> __device__ __forceinline__ void cp_wait() {
    asm volatile("cp.async.wait_group %0;\n" :: "n"(N) : "memory");
}
__device__ __forceinline__ void ldsm_x4(uint32_t* r, uint32_t addr) {
    asm volatile("ldmatrix.sync.aligned.m8n8.x4.shared.b16 {%0,%1,%2,%3}, [%4];\n"
                 : "=r"(r[0]), "=r"(r[1]), "=r"(r[2]), "=r"(r[3]) : "r"(addr));
}
__device__ __forceinline__ void mma_16816(float* c, const uint32_t* a, const uint32_t* b) {
    asm volatile("mma.sync.aligned.m16n8k16.row.col.f32.bf16.bf16.f32 "
                 "{%0,%1,%2,%3}, {%4,%5,%6,%7}, {%8,%9}, {%0,%1,%2,%3};\n"
                 : "+f"(c[0]), "+f"(c[1]), "+f"(c[2]), "+f"(c[3])
                 : "r"(a[0]), "r"(a[1]), "r"(a[2]), "r"(a[3]), "r"(b[0]), "r"(b[1]));
}
__device__ __forceinline__ float tanh_fast(float x) {
    float y;
    asm("tanh.approx.f32 %0, %1;" : "=f"(y) : "f"(x));
    return y;
}

// ---------------- scratch (device globals) ----------------------------------
__device__ __align__(16) float g_hs[(size_t)BB * NN * DD];   // [B,N,D]
__device__ __align__(16) float g_m[BB * TWO_D];              // [B,2D] fp32
__device__ __align__(16) float g_c[BB * DD];                 // [B,D]
__device__ __align__(16) float g_query[BB * DD];             // [B,D]
// bf16 hi/lo operand copies
__device__ __align__(16) __nv_bfloat16 g_x_hi[(size_t)BB * NN * DD];
__device__ __align__(16) __nv_bfloat16 g_x_lo[(size_t)BB * NN * DD];
__device__ __align__(16) __nv_bfloat16 g_m_hi[BB * TWO_D];
__device__ __align__(16) __nv_bfloat16 g_m_lo[BB * TWO_D];
// packed transposed weights bf16 hi/lo
__device__ __align__(16) __nv_bfloat16 g_fc_hi[DD * DD];         // [N][K]
__device__ __align__(16) __nv_bfloat16 g_fc_lo[DD * DD];
__device__ __align__(16) __nv_bfloat16 g_wg_hi[4 * DD * TWO_D];  // [2048][1024], cols 4j+g
__device__ __align__(16) __nv_bfloat16 g_wg_lo[4 * DD * TWO_D];
__device__ __align__(16) __nv_bfloat16 g_q_hi[DD * DD];          // [N][K]
__device__ __align__(16) __nv_bfloat16 g_q_lo[DD * DD];

__device__ __forceinline__ float sigmoidf_(float x) { return 1.0f / (1.0f + expf(-x)); }

// ---------------- tile copy: gmem bf16 [rows][ld] -> smem SW128 -------------
template<int ROWS>
__device__ __forceinline__ void copy_tile(uint32_t sbase, const __nv_bfloat16* __restrict__ g,
                                          int ldg, int r0, int k0, int t) {
#pragma unroll
    for (int v = t; v < ROWS * 8; v += 256) {
        int row = v >> 3, ch = v & 7;
        uint32_t off = SWZ((uint32_t)(row * 128 + ch * 16));
        cp_async16(sbase + off, g + (size_t)(r0 + row) * ldg + k0 + ch * 8);
    }
}

// ---------------- bf16-split HMMA GEMM --------------------------------------
// C[M,N] = (Ahi+Alo)[M,K] @ (Bhi+Blo)^T, B stored [N][K]. 3-term split, fp32 acc.
// 3-stage cp.async ring, ONE __syncthreads per K-block.
// FUSE=true: gate path — cols interleaved 4j+g; epilogue does the LSTM combine.
template<int BM, int BN, int WM, int WN, bool FUSE, int OCC>
__global__ void __launch_bounds__(256, OCC)
mma_gemm_kernel(int K,
                const __nv_bfloat16* __restrict__ Ahi, const __nv_bfloat16* __restrict__ Alo, int lda,
                const __nv_bfloat16* __restrict__ Bhi, const __nv_bfloat16* __restrict__ Blo, int ldb,
                float* __restrict__ C, int ldc, const float* __restrict__ bias,
                const float* __restrict__ bi, const float* __restrict__ bf,
                const float* __restrict__ bc, const float* __restrict__ bo)
{
    constexpr int WTM = BM / WM, WTN = BN / WN;
    constexpr int MT = WTM / 16, NT = WTN / 8, NP = NT / 2;
    constexpr int STAGE = (2 * BM + 2 * BN) * 128;
    static_assert(WM * WN == 8 && MT >= 1 && NP >= 1, "cfg");

    extern __shared__ char smem[];
    const int t = threadIdx.x, lane = t & 31, wid = t >> 5;
    const int wm = wid % WM, wn = wid / WM;
    const int m0 = blockIdx.y * BM, n0 = blockIdx.x * BN;
    const uint32_t sbase = (uint32_t)__cvta_generic_to_shared(smem);

    float c[MT][NT][4];
#pragma unroll
    for (int i = 0; i < MT; i++)
#pragma unroll
        for (int j = 0; j < NT; j++)
#pragma unroll
            for (int q = 0; q < 4; q++) c[i][j][q] = 0.0f;

    const int NB = K >> 6;

    auto issue = [&](int kb, int buf) {
        uint32_t st = sbase + (uint32_t)buf * STAGE;
        copy_tile<BM>(st,                           Ahi, lda, m0, kb * 64, t);
        copy_tile<BM>(st + BM * 128,                Alo, lda, m0, kb * 64, t);
        copy_tile<BN>(st + 2 * BM * 128,            Bhi, ldb, n0, kb * 64, t);
        copy_tile<BN>(st + 2 * BM * 128 + BN * 128, Blo, ldb, n0, kb * 64, t);
        cp_commit();
    };

    // prime 2 stages of the 3-stage ring
    issue(0, 0);
    issue(1, 1);

    for (int kb = 0; kb < NB; kb++) {
        if (kb + 1 < NB) cp_wait<1>(); else cp_wait<0>();
        __syncthreads();
        // refill stage (kb+2)%3 == (kb-1)%3: its readers all passed the barrier
        if (kb + 2 < NB) issue(kb + 2, (kb + 2) % 3);

        const uint32_t st  = sbase + (uint32_t)(kb % 3) * STAGE;
        const uint32_t aHi = st, aLo = st + BM * 128;
        const uint32_t bHi = st + 2 * BM * 128, bLo = bHi + BN * 128;

#pragma unroll
        for (int s = 0; s < 4; s++) {
            uint32_t ahf[MT][4], alf[MT][4];
            const int      arow  = wm * WTM + (lane & 15);
            const uint32_t abyte = s * 32 + ((lane >> 4) << 4);
#pragma unroll
            for (int i = 0; i < MT; i++) {
                uint32_t off = SWZ((uint32_t)((arow + i * 16) * 128) + abyte);
                ldsm_x4(ahf[i], aHi + off);
                ldsm_x4(alf[i], aLo + off);
            }
            uint32_t bhf[NP][4], blf[NP][4];
            const int      brow  = wn * WTN + ((lane >> 4) << 3) + (lane & 7);
            const uint32_t bbyte = s * 32 + (((lane >> 3) & 1) << 4);
#pragma unroll
            for (int p = 0; p < NP; p++) {
                uint32_t off = SWZ((uint32_t)((brow + p * 16) * 128) + bbyte);
                ldsm_x4(bhf[p], bHi + off);
                ldsm_x4(blf[p], bLo + off);
            }
#pragma unroll
            for (int i = 0; i < MT; i++)
#pragma unroll
                for (int j = 0; j < NT; j++) {
                    const uint32_t* bh = &bhf[j >> 1][(j & 1) * 2];
                    const uint32_t* bl = &blf[j >> 1][(j & 1) * 2];
                    mma_16816(c[i][j], ahf[i], bh);
                    mma_16816(c[i][j], ahf[i], bl);
                    mma_16816(c[i][j], alf[i], bh);
                }
        }
        // no tail barrier: 3-stage ring makes the next refill WAR-safe
    }

    const int wr = m0 + wm * WTM, wc = n0 + wn * WTN;
    if constexpr (FUSE) {
        const int q = lane & 3;
        const bool odd = (q & 1) != 0;
#pragma unroll
        for (int i = 0; i < MT; i++) {
            const int r = wr + i * 16 + (lane >> 2);
#pragma unroll
            for (int j = 0; j < NT; j++) {
                const int Gc = wc + j * 8 + q * 2;
                const int jj = Gc >> 2;
                float v0 = c[i][j][0], v1 = c[i][j][1];
                float v2 = c[i][j][2], v3 = c[i][j][3];
                if (!odd) { v0 += bi[jj]; v1 += bf[jj]; v2 += bi[jj]; v3 += bf[jj]; }
                else      { v0 += bc[jj]; v1 += bo[jj]; v2 += bc[jj]; v3 += bo[jj]; }
                float u0 = __shfl_xor_sync(0xFFFFFFFF, v0, 1);
                float u1 = __shfl_xor_sync(0xFFFFFFFF, v1, 1);
                float u2 = __shfl_xor_sync(0xFFFFFFFF, v2, 1);
                float u3 = __shfl_xor_sync(0xFFFFFFFF, v3, 1);
                const int row = odd ? (r + 8) : r;
                const float ip_ = odd ? u2 : v0;
                const float fp_ = odd ? u3 : v1;
                const float cp_ = odd ? v2 : u0;
                const float op_ = odd ? v3 : u1;
                const float cold = g_c[row * DD + jj];
                const float cn = sigmoidf_(fp_) * cold + sigmoidf_(ip_) * tanhf(cp_);
                g_c[row * DD + jj] = cn;
                const float mv = sigmoidf_(op_) * tanhf(cn);
                g_m[row * TWO_D + jj] = mv;
                const __nv_bfloat16 h = __float2bfloat16_rn(mv);
                g_m_hi[row * TWO_D + jj] = h;
                g_m_lo[row * TWO_D + jj] = __float2bfloat16_rn(mv - __bfloat162float(h));
            }
        }
    } else {
#pragma unroll
        for (int i = 0; i < MT; i++) {
            int r0 = wr + i * 16 + (lane >> 2);
#pragma unroll
            for (int j = 0; j < NT; j++) {
                int col = wc + j * 8 + (lane & 3) * 2;   // GLOBAL col (includes n0)
                float bx = 0.0f, by = 0.0f;
                if (bias) { bx = bias[col]; by = bias[col + 1]; }
                float2 v0 = make_float2(c[i][j][0] + bx, c[i][j][1] + by);
                float2 v1 = make_float2(c[i][j][2] + bx, c[i][j][3] + by);
                *(float2*)&C[(size_t)r0 * ldc + col]       = v0;
                *(float2*)&C[(size_t)(r0 + 8) * ldc + col] = v1;
            }
        }
    }
}

// ---------------- conversion / pack kernels ---------------------------------
__global__ void conv_x_kernel(const float* __restrict__ X) {
    int i = blockIdx.x * blockDim.x + threadIdx.x;
    const int n4 = (int)((size_t)BB * NN * DD / 4);
    if (i >= n4) return;
    float4 x = ((const float4*)X)[i];
    __nv_bfloat16 h0 = __float2bfloat16_rn(x.x), h1 = __float2bfloat16_rn(x.y);
    __nv_bfloat16 h2 = __float2bfloat16_rn(x.z), h3 = __float2bfloat16_rn(x.w);
    __nv_bfloat162 hh0(h0, h1), hh1(h2, h3);
    __nv_bfloat162 ll0(__float2bfloat16_rn(x.x - __bfloat162float(h0)),
                       __float2bfloat16_rn(x.y - __bfloat162float(h1)));
    __nv_bfloat162 ll1(__float2bfloat16_rn(x.z - __bfloat162float(h2)),
                       __float2bfloat16_rn(x.w - __bfloat162float(h3)));
    ((uint2*)g_x_hi)[i] = make_uint2(*(uint32_t*)&hh0, *(uint32_t*)&hh1);
    ((uint2*)g_x_lo)[i] = make_uint2(*(uint32_t*)&ll0, *(uint32_t*)&ll1);
}

// tiled transpose pack: w[K][N] -> out_hi/lo rows (n*rowMul+rowOff), cols k
__global__ void packT_kernel(const float* __restrict__ w,
                             __nv_bfloat16* __restrict__ hi, __nv_bfloat16* __restrict__ lo,
                             int K, int N, int rowMul, int rowOff) {
    __shared__ float s[32][33];
    const int n0 = blockIdx.x * 32, k0 = blockIdx.y * 32;
    const int tx = threadIdx.x & 31, ty = threadIdx.x >> 5;   // 32 x 8
#pragma unroll
    for (int i = 0; i < 4; i++) {
        int k = k0 + ty + i * 8;
        s[ty + i * 8][tx] = w[(size_t)k * N + n0 + tx];
    }
    __syncthreads();
#pragma unroll
    for (int i = 0; i < 4; i++) {
        int n = n0 + ty + i * 8;
        float x = s[tx][ty + i * 8];
        __nv_bfloat16 h = __float2bfloat16_rn(x);
        size_t o = (size_t)(n * rowMul + rowOff) * K + k0 + tx;
        hi[o] = h;
        lo[o] = __float2bfloat16_rn(x - __bfloat162float(h));
    }
}

// ---------------- elementwise / attention ------------------------------------
__global__ void zero_mc_kernel() {
    int i = blockIdx.x * blockDim.x + threadIdx.x;
    if (i < BB * TWO_D) {
        g_m[i] = 0.0f;
        g_m_hi[i] = __float2bfloat16_rn(0.0f);
        g_m_lo[i] = __float2bfloat16_rn(0.0f);
    }
    if (i < BB * DD) g_c[i] = 0.0f;
}

// energies -> softmax -> read (query from g_query), MUFU tanh in energies
__global__ void __launch_bounds__(128)
attention_kernel(const float* __restrict__ mask, const float* __restrict__ att_v) {
    __shared__ float hs_s[NN][DH + 1];
    __shared__ float qv[DH];
    __shared__ float av[DH];
    __shared__ float red[NN];
    __shared__ float attn[NN];

    const int t = threadIdx.x;
    const int b = blockIdx.x >> 3;
    const int h = blockIdx.x & 7;

    const float* hs_base = g_hs + (size_t)b * NN * DD + h * DH;
    for (int i = t; i < NN * DH; i += 128) {
        int n = i >> 6, d = i & 63;
        hs_s[n][d] = hs_base[(size_t)n * DD + d];
    }
    if (t < DH) {
        qv[t] = g_query[b * DD + h * DH + t];
        av[t] = att_v[h * DH + t];
    }
    __syncthreads();

    float e = 0.0f;
#pragma unroll 8
    for (int d = 0; d < DH; d++) e += tanh_fast(qv[d] + hs_s[t][d]) * av[d];
    e += (1.0f - mask[b * NN + t]) * (-1e10f);

    red[t] = e;
    __syncthreads();
#pragma unroll
    for (int s = 64; s > 0; s >>= 1) {
        if (t < s) red[t] = fmaxf(red[t], red[t + s]);
        __syncthreads();
    }
    const float mx = red[0];
    __syncthreads();

    float p = expf(e - mx);
    attn[t] = p; red[t] = p;
    __syncthreads();
#pragma unroll
    for (int s = 64; s > 0; s >>= 1) {
        if (t < s) red[t] += red[t + s];
        __syncthreads();
    }
    const float inv_sum = 1.0f / red[0];
    __syncthreads();
    attn[t] *= inv_sum;
    __syncthreads();

    if (t < DH) {
        float r = 0.0f;
#pragma unroll 8
        for (int n = 0; n < NN; n++) r += attn[n] * hs_s[n][t];
        int col = DD + h * DH + t;
        g_m[b * TWO_D + col] = r;
        __nv_bfloat16 hh = __float2bfloat16_rn(r);
        g_m_hi[b * TWO_D + col] = hh;
        g_m_lo[b * TWO_D + col] = __float2bfloat16_rn(r - __bfloat162float(hh));
    }
}

__global__ void copy_out_kernel(float* __restrict__ out) {
    int i = blockIdx.x * blockDim.x + threadIdx.x;
    if (i < BB * TWO_D) out[i] = g_m[i];
}

// ---------------- launcher ----------------------------------------------------
extern "C" void kernel_launch(void* const* d_in, const int* in_sizes, int n_in,
                              void* d_out, int out_size) {
    const float* X     = (const float*)d_in[0];
    const float* mask  = (const float*)d_in[1];
    const float* fc_w  = (const float*)d_in[2];
    const float* fc_b  = (const float*)d_in[3];
    const float* w_im  = (const float*)d_in[4];
    const float* b_i   = (const float*)d_in[5];
    const float* w_fm  = (const float*)d_in[6];
    const float* b_f   = (const float*)d_in[7];
    const float* w_cm  = (const float*)d_in[8];
    const float* b_c   = (const float*)d_in[9];
    const float* w_om  = (const float*)d_in[10];
    const float* b_o   = (const float*)d_in[11];
    const float* m2q   = (const float*)d_in[12];
    const float* att_v = (const float*)d_in[13];
    float* out = (float*)d_out;

    float *p_hs, *p_query;
    __nv_bfloat16 *p_x_hi, *p_x_lo, *p_m_hi, *p_m_lo;
    __nv_bfloat16 *p_fc_hi, *p_fc_lo, *p_wg_hi, *p_wg_lo, *p_q_hi, *p_q_lo;
    cudaGetSymbolAddress((void**)&p_hs,    g_hs);
    cudaGetSymbolAddress((void**)&p_query, g_query);
    cudaGetSymbolAddress((void**)&p_x_hi,  g_x_hi);
    cudaGetSymbolAddress((void**)&p_x_lo,  g_x_lo);
    cudaGetSymbolAddress((void**)&p_m_hi,  g_m_hi);
    cudaGetSymbolAddress((void**)&p_m_lo,  g_m_lo);
    cudaGetSymbolAddress((void**)&p_fc_hi, g_fc_hi);
    cudaGetSymbolAddress((void**)&p_fc_lo, g_fc_lo);
    cudaGetSymbolAddress((void**)&p_wg_hi, g_wg_hi);
    cudaGetSymbolAddress((void**)&p_wg_lo, g_wg_lo);
    cudaGetSymbolAddress((void**)&p_q_hi,  g_q_hi);
    cudaGetSymbolAddress((void**)&p_q_lo,  g_q_lo);

    // 3-stage smem sizes
    const int SM_PROJ  = (2 * 128 + 2 * 64) * 128 * 3;  // 147456 -> 1 CTA/SM
    const int SM_GATE  = (2 * 64  + 2 * 64) * 128 * 3;  // 98304  -> 2 CTAs/SM
    const int SM_QUERY = (2 * 32  + 2 * 64) * 128 * 3;  // 73728  -> 2 CTAs/SM
    cudaFuncSetAttribute((const void*)mma_gemm_kernel<128, 64, 2, 4, false, 1>,
                         cudaFuncAttributeMaxDynamicSharedMemorySize, SM_PROJ);
    cudaFuncSetAttribute((const void*)mma_gemm_kernel<64, 64, 2, 4, true, 2>,
                         cudaFuncAttributeMaxDynamicSharedMemorySize, SM_GATE);
    cudaFuncSetAttribute((const void*)mma_gemm_kernel<32, 64, 2, 4, false, 2>,
                         cudaFuncAttributeMaxDynamicSharedMemorySize, SM_QUERY);

    zero_mc_kernel<<<(BB * TWO_D + 255) / 256, 256>>>();
    conv_x_kernel<<<((int)((size_t)BB * NN * DD / 4) + 255) / 256, 256>>>(X);
    dim3 gfc(DD / 32, DD / 32);
    packT_kernel<<<gfc, 256>>>(fc_w, p_fc_hi, p_fc_lo, DD, DD, 1, 0);
    packT_kernel<<<gfc, 256>>>(m2q,  p_q_hi,  p_q_lo,  DD, DD, 1, 0);
    dim3 gg(DD / 32, TWO_D / 32);
    packT_kernel<<<gg, 256>>>(w_im, p_wg_hi, p_wg_lo, TWO_D, DD, 4, 0);

    // projection GEMM: hs = X @ fc_w + fc_b
    {
        dim3 grid(DD / 64, (BB * NN) / 128);
        mma_gemm_kernel<128, 64, 2, 4, false, 1><<<grid, 256, SM_PROJ>>>(
            DD, p_x_hi, p_x_lo, DD, p_fc_hi, p_fc_lo, DD, p_hs, DD, fc_b,
            nullptr, nullptr, nullptr, nullptr);
    }

    // remaining gate packs (independent of projection)
    packT_kernel<<<gg, 256>>>(w_fm, p_wg_hi, p_wg_lo, TWO_D, DD, 4, 1);
    packT_kernel<<<gg, 256>>>(w_cm, p_wg_hi, p_wg_lo, TWO_D, DD, 4, 2);
    packT_kernel<<<gg, 256>>>(w_om, p_wg_hi, p_wg_lo, TWO_D, DD, 4, 3);

    for (int step = 0; step < STEPS; step++) {
        // gates + fused combine: m[512,1024] @ Wg^T -> c, m_lstm (+hi/lo)
        {
            dim3 grid((4 * DD) / 64, BB / 64);
            mma_gemm_kernel<64, 64, 2, 4, true, 2><<<grid, 256, SM_GATE>>>(
                TWO_D, p_m_hi, p_m_lo, TWO_D, p_wg_hi, p_wg_lo, TWO_D,
                nullptr, 0, nullptr, b_i, b_f, b_c, b_o);
        }
        // query = m_lstm @ m2q  (tiled HMMA GEMM, A = m_hi/lo[:, :512])
        {
            dim3 grid(DD / 64, BB / 32);
            mma_gemm_kernel<32, 64, 2, 4, false, 2><<<grid, 256, SM_QUERY>>>(
                DD, p_m_hi, p_m_lo, TWO_D, p_q_hi, p_q_lo, DD,
                p_query, DD, nullptr, nullptr, nullptr, nullptr, nullptr);
        }
        attention_kernel<<<BB * HH, 128>>>(mask, att_v);
    }

    copy_out_kernel<<<(BB * TWO_D + 255) / 256, 256>>>(out);
}

// round 13
// speedup vs baseline: 1.0471x; 1.0471x over previous
#include <cuda_runtime.h>
#include <cuda_bf16.h>
#include <math.h>
#include <stdint.h>

// Problem constants
#define BB 512
#define NN 128
#define DD 512
#define HH 8
#define DH 64
#define TWO_D 1024
#define STEPS 6

#define SWZ(off) ((off) ^ (((off) >> 3) & 0x70))

// ---------------- PTX helpers (sm_80+ features only) ------------------------
__device__ __forceinline__ void cp_async16(uint32_t smem_addr, const void* gptr) {
    asm volatile("cp.async.cg.shared.global [%0], [%1], 16;\n"
                 :: "r"(smem_addr), "l"(gptr));
}
__device__ __forceinline__ void cp_commit() {
    asm volatile("cp.async.commit_group;\n" ::: "memory");
}
template<int N> __device__ __forceinline__ void cp_wait() {
    asm volatile("cp.async.wait_group %0;\n" :: "n"(N) : "memory");
}
__device__ __forceinline__ void ldsm_x4(uint32_t* r, uint32_t addr) {
    asm volatile("ldmatrix.sync.aligned.m8n8.x4.shared.b16 {%0,%1,%2,%3}, [%4];\n"
                 : "=r"(r[0]), "=r"(r[1]), "=r"(r[2]), "=r"(r[3]) : "r"(addr));
}
__device__ __forceinline__ void mma_16816(float* c, const uint32_t* a, const uint32_t* b) {
    asm volatile("mma.sync.aligned.m16n8k16.row.col.f32.bf16.bf16.f32 "
                 "{%0,%1,%2,%3}, {%4,%5,%6,%7}, {%8,%9}, {%0,%1,%2,%3};\n"
                 : "+f"(c[0]), "+f"(c[1]), "+f"(c[2]), "+f"(c[3])
                 : "r"(a[0]), "r"(a[1]), "r"(a[2]), "r"(a[3]), "r"(b[0]), "r"(b[1]));
}
__device__ __forceinline__ float tanh_fast(float x) {
    float y;
    asm("tanh.approx.f32 %0, %1;" : "=f"(y) : "f"(x));
    return y;
}

// ---------------- scratch (device globals) ----------------------------------
__device__ __align__(16) float g_hs[(size_t)BB * NN * DD];   // [B,N,D]
__device__ __align__(16) float g_m[BB * TWO_D];              // [B,2D] fp32
__device__ __align__(16) float g_c[BB * DD];                 // [B,D]
__device__ __align__(16) float g_query[BB * DD];             // [B,D]
// bf16 hi/lo operand copies
__device__ __align__(16) __nv_bfloat16 g_x_hi[(size_t)BB * NN * DD];
__device__ __align__(16) __nv_bfloat16 g_x_lo[(size_t)BB * NN * DD];
__device__ __align__(16) __nv_bfloat16 g_m_hi[BB * TWO_D];
__device__ __align__(16) __nv_bfloat16 g_m_lo[BB * TWO_D];
// packed transposed weights bf16 hi/lo
__device__ __align__(16) __nv_bfloat16 g_fc_hi[DD * DD];         // [N][K]
__device__ __align__(16) __nv_bfloat16 g_fc_lo[DD * DD];
__device__ __align__(16) __nv_bfloat16 g_wg_hi[4 * DD * TWO_D];  // [2048][1024], cols 4j+g
__device__ __align__(16) __nv_bfloat16 g_wg_lo[4 * DD * TWO_D];
__device__ __align__(16) __nv_bfloat16 g_q_hi[DD * DD];          // [N][K]
__device__ __align__(16) __nv_bfloat16 g_q_lo[DD * DD];

__device__ __forceinline__ float sigmoidf_(float x) { return 1.0f / (1.0f + expf(-x)); }

// ---------------- tile copy: gmem bf16 [rows][ld] -> smem SW128 -------------
template<int ROWS>
__device__ __forceinline__ void copy_tile(uint32_t sbase, const __nv_bfloat16* __restrict__ g,
                                          int ldg, int r0, int k0, int t) {
#pragma unroll
    for (int v = t; v < ROWS * 8; v += 256) {
        int row = v >> 3, ch = v & 7;
        uint32_t off = SWZ((uint32_t)(row * 128 + ch * 16));
        cp_async16(sbase + off, g + (size_t)(r0 + row) * ldg + k0 + ch * 8);
    }
}

// ---------------- bf16-split HMMA GEMM --------------------------------------
// C[M,N] = (Ahi+Alo)[M,K] @ (Bhi+Blo)^T, B stored [N][K]. 3-term split, fp32 acc.
// STG=2: double buffer, 2 barriers/K-block. STG=3: ring, 1 barrier/K-block.
// FUSE=true: gate path — cols interleaved 4j+g; epilogue does the LSTM combine.
template<int BM, int BN, int WM, int WN, bool FUSE, int OCC, int STG>
__global__ void __launch_bounds__(256, OCC)
mma_gemm_kernel(int K,
                const __nv_bfloat16* __restrict__ Ahi, const __nv_bfloat16* __restrict__ Alo, int lda,
                const __nv_bfloat16* __restrict__ Bhi, const __nv_bfloat16* __restrict__ Blo, int ldb,
                float* __restrict__ C, int ldc, const float* __restrict__ bias,
                const float* __restrict__ bi, const float* __restrict__ bf,
                const float* __restrict__ bc, const float* __restrict__ bo)
{
    constexpr int WTM = BM / WM, WTN = BN / WN;
    constexpr int MT = WTM / 16, NT = WTN / 8, NP = NT / 2;
    constexpr int STAGE = (2 * BM + 2 * BN) * 128;
    static_assert(WM * WN == 8 && MT >= 1 && NP >= 1, "cfg");
    static_assert(STG == 2 || STG == 3, "stages");

    extern __shared__ char smem[];
    const int t = threadIdx.x, lane = t & 31, wid = t >> 5;
    const int wm = wid % WM, wn = wid / WM;
    const int m0 = blockIdx.y * BM, n0 = blockIdx.x * BN;
    const uint32_t sbase = (uint32_t)__cvta_generic_to_shared(smem);

    float c[MT][NT][4];
#pragma unroll
    for (int i = 0; i < MT; i++)
#pragma unroll
        for (int j = 0; j < NT; j++)
#pragma unroll
            for (int q = 0; q < 4; q++) c[i][j][q] = 0.0f;

    const int NB = K >> 6;

    auto issue = [&](int kb, int buf) {
        uint32_t st = sbase + (uint32_t)buf * STAGE;
        copy_tile<BM>(st,                           Ahi, lda, m0, kb * 64, t);
        copy_tile<BM>(st + BM * 128,                Alo, lda, m0, kb * 64, t);
        copy_tile<BN>(st + 2 * BM * 128,            Bhi, ldb, n0, kb * 64, t);
        copy_tile<BN>(st + 2 * BM * 128 + BN * 128, Blo, ldb, n0, kb * 64, t);
        cp_commit();
    };

    auto compute_block = [&](uint32_t st) {
        const uint32_t aHi = st, aLo = st + BM * 128;
        const uint32_t bHi = st + 2 * BM * 128, bLo = bHi + BN * 128;
#pragma unroll
        for (int s = 0; s < 4; s++) {
            uint32_t ahf[MT][4], alf[MT][4];
            const int      arow  = wm * WTM + (lane & 15);
            const uint32_t abyte = s * 32 + ((lane >> 4) << 4);
#pragma unroll
            for (int i = 0; i < MT; i++) {
                uint32_t off = SWZ((uint32_t)((arow + i * 16) * 128) + abyte);
                ldsm_x4(ahf[i], aHi + off);
                ldsm_x4(alf[i], aLo + off);
            }
            uint32_t bhf[NP][4], blf[NP][4];
            const int      brow  = wn * WTN + ((lane >> 4) << 3) + (lane & 7);
            const uint32_t bbyte = s * 32 + (((lane >> 3) & 1) << 4);
#pragma unroll
            for (int p = 0; p < NP; p++) {
                uint32_t off = SWZ((uint32_t)((brow + p * 16) * 128) + bbyte);
                ldsm_x4(bhf[p], bHi + off);
                ldsm_x4(blf[p], bLo + off);
            }
#pragma unroll
            for (int i = 0; i < MT; i++)
#pragma unroll
                for (int j = 0; j < NT; j++) {
                    const uint32_t* bh = &bhf[j >> 1][(j & 1) * 2];
                    const uint32_t* bl = &blf[j >> 1][(j & 1) * 2];
                    mma_16816(c[i][j], ahf[i], bh);
                    mma_16816(c[i][j], ahf[i], bl);
                    mma_16816(c[i][j], alf[i], bh);
                }
        }
    };

    issue(0, 0);
    issue(1, 1);

    if constexpr (STG == 2) {
        for (int kb = 0; kb < NB; kb++) {
            if (kb + 1 < NB) cp_wait<1>(); else cp_wait<0>();
            __syncthreads();
            compute_block(sbase + (uint32_t)(kb & 1) * STAGE);
            __syncthreads();
            if (kb + 2 < NB) issue(kb + 2, kb & 1);
        }
    } else {
        for (int kb = 0; kb < NB; kb++) {
            if (kb + 1 < NB) cp_wait<1>(); else cp_wait<0>();
            __syncthreads();
            if (kb + 2 < NB) issue(kb + 2, (kb + 2) % 3);
            compute_block(sbase + (uint32_t)(kb % 3) * STAGE);
            // no tail barrier: ring stage (kb+2)%3 readers passed the barrier
        }
    }

    const int wr = m0 + wm * WTM, wc = n0 + wn * WTN;
    if constexpr (FUSE) {
        const int q = lane & 3;
        const bool odd = (q & 1) != 0;
#pragma unroll
        for (int i = 0; i < MT; i++) {
            const int r = wr + i * 16 + (lane >> 2);
#pragma unroll
            for (int j = 0; j < NT; j++) {
                const int Gc = wc + j * 8 + q * 2;
                const int jj = Gc >> 2;
                float v0 = c[i][j][0], v1 = c[i][j][1];
                float v2 = c[i][j][2], v3 = c[i][j][3];
                if (!odd) { v0 += bi[jj]; v1 += bf[jj]; v2 += bi[jj]; v3 += bf[jj]; }
                else      { v0 += bc[jj]; v1 += bo[jj]; v2 += bc[jj]; v3 += bo[jj]; }
                float u0 = __shfl_xor_sync(0xFFFFFFFF, v0, 1);
                float u1 = __shfl_xor_sync(0xFFFFFFFF, v1, 1);
                float u2 = __shfl_xor_sync(0xFFFFFFFF, v2, 1);
                float u3 = __shfl_xor_sync(0xFFFFFFFF, v3, 1);
                const int row = odd ? (r + 8) : r;
                const float ip_ = odd ? u2 : v0;
                const float fp_ = odd ? u3 : v1;
                const float cp_ = odd ? v2 : u0;
                const float op_ = odd ? v3 : u1;
                const float cold = g_c[row * DD + jj];
                const float cn = sigmoidf_(fp_) * cold + sigmoidf_(ip_) * tanhf(cp_);
                g_c[row * DD + jj] = cn;
                const float mv = sigmoidf_(op_) * tanhf(cn);
                g_m[row * TWO_D + jj] = mv;
                const __nv_bfloat16 h = __float2bfloat16_rn(mv);
                g_m_hi[row * TWO_D + jj] = h;
                g_m_lo[row * TWO_D + jj] = __float2bfloat16_rn(mv - __bfloat162float(h));
            }
        }
    } else {
#pragma unroll
        for (int i = 0; i < MT; i++) {
            int r0 = wr + i * 16 + (lane >> 2);
#pragma unroll
            for (int j = 0; j < NT; j++) {
                int col = wc + j * 8 + (lane & 3) * 2;   // GLOBAL col (includes n0)
                float bx = 0.0f, by = 0.0f;
                if (bias) { bx = bias[col]; by = bias[col + 1]; }
                float2 v0 = make_float2(c[i][j][0] + bx, c[i][j][1] + by);
                float2 v1 = make_float2(c[i][j][2] + bx, c[i][j][3] + by);
                *(float2*)&C[(size_t)r0 * ldc + col]       = v0;
                *(float2*)&C[(size_t)(r0 + 8) * ldc + col] = v1;
            }
        }
    }
}

// ---------------- conversion / pack kernels ---------------------------------
__global__ void conv_x_kernel(const float* __restrict__ X) {
    int i = blockIdx.x * blockDim.x + threadIdx.x;
    const int n4 = (int)((size_t)BB * NN * DD / 4);
    if (i >= n4) return;
    float4 x = ((const float4*)X)[i];
    __nv_bfloat16 h0 = __float2bfloat16_rn(x.x), h1 = __float2bfloat16_rn(x.y);
    __nv_bfloat16 h2 = __float2bfloat16_rn(x.z), h3 = __float2bfloat16_rn(x.w);
    __nv_bfloat162 hh0(h0, h1), hh1(h2, h3);
    __nv_bfloat162 ll0(__float2bfloat16_rn(x.x - __bfloat162float(h0)),
                       __float2bfloat16_rn(x.y - __bfloat162float(h1)));
    __nv_bfloat162 ll1(__float2bfloat16_rn(x.z - __bfloat162float(h2)),
                       __float2bfloat16_rn(x.w - __bfloat162float(h3)));
    ((uint2*)g_x_hi)[i] = make_uint2(*(uint32_t*)&hh0, *(uint32_t*)&hh1);
    ((uint2*)g_x_lo)[i] = make_uint2(*(uint32_t*)&ll0, *(uint32_t*)&ll1);
}

// tiled transpose pack: w[K][N] -> out_hi/lo rows (n*rowMul+rowOff), cols k
__global__ void packT_kernel(const float* __restrict__ w,
                             __nv_bfloat16* __restrict__ hi, __nv_bfloat16* __restrict__ lo,
                             int K, int N, int rowMul, int rowOff) {
    __shared__ float s[32][33];
    const int n0 = blockIdx.x * 32, k0 = blockIdx.y * 32;
    const int tx = threadIdx.x & 31, ty = threadIdx.x >> 5;   // 32 x 8
#pragma unroll
    for (int i = 0; i < 4; i++) {
        int k = k0 + ty + i * 8;
        s[ty + i * 8][tx] = w[(size_t)k * N + n0 + tx];
    }
    __syncthreads();
#pragma unroll
    for (int i = 0; i < 4; i++) {
        int n = n0 + ty + i * 8;
        float x = s[tx][ty + i * 8];
        __nv_bfloat16 h = __float2bfloat16_rn(x);
        size_t o = (size_t)(n * rowMul + rowOff) * K + k0 + tx;
        hi[o] = h;
        lo[o] = __float2bfloat16_rn(x - __bfloat162float(h));
    }
}

// ---------------- elementwise / attention ------------------------------------
__global__ void zero_mc_kernel() {
    int i = blockIdx.x * blockDim.x + threadIdx.x;
    if (i < BB * TWO_D) {
        g_m[i] = 0.0f;
        g_m_hi[i] = __float2bfloat16_rn(0.0f);
        g_m_lo[i] = __float2bfloat16_rn(0.0f);
    }
    if (i < BB * DD) g_c[i] = 0.0f;
}

// energies -> softmax -> read (query from g_query), MUFU tanh in energies
__global__ void __launch_bounds__(128)
attention_kernel(const float* __restrict__ mask, const float* __restrict__ att_v) {
    __shared__ float hs_s[NN][DH + 1];
    __shared__ float qv[DH];
    __shared__ float av[DH];
    __shared__ float red[NN];
    __shared__ float attn[NN];

    const int t = threadIdx.x;
    const int b = blockIdx.x >> 3;
    const int h = blockIdx.x & 7;

    const float* hs_base = g_hs + (size_t)b * NN * DD + h * DH;
    for (int i = t; i < NN * DH; i += 128) {
        int n = i >> 6, d = i & 63;
        hs_s[n][d] = hs_base[(size_t)n * DD + d];
    }
    if (t < DH) {
        qv[t] = g_query[b * DD + h * DH + t];
        av[t] = att_v[h * DH + t];
    }
    __syncthreads();

    float e = 0.0f;
#pragma unroll 8
    for (int d = 0; d < DH; d++) e += tanh_fast(qv[d] + hs_s[t][d]) * av[d];
    e += (1.0f - mask[b * NN + t]) * (-1e10f);

    red[t] = e;
    __syncthreads();
#pragma unroll
    for (int s = 64; s > 0; s >>= 1) {
        if (t < s) red[t] = fmaxf(red[t], red[t + s]);
        __syncthreads();
    }
    const float mx = red[0];
    __syncthreads();

    float p = expf(e - mx);
    attn[t] = p; red[t] = p;
    __syncthreads();
#pragma unroll
    for (int s = 64; s > 0; s >>= 1) {
        if (t < s) red[t] += red[t + s];
        __syncthreads();
    }
    const float inv_sum = 1.0f / red[0];
    __syncthreads();
    attn[t] *= inv_sum;
    __syncthreads();

    if (t < DH) {
        float r = 0.0f;
#pragma unroll 8
        for (int n = 0; n < NN; n++) r += attn[n] * hs_s[n][t];
        int col = DD + h * DH + t;
        g_m[b * TWO_D + col] = r;
        __nv_bfloat16 hh = __float2bfloat16_rn(r);
        g_m_hi[b * TWO_D + col] = hh;
        g_m_lo[b * TWO_D + col] = __float2bfloat16_rn(r - __bfloat162float(hh));
    }
}

__global__ void copy_out_kernel(float* __restrict__ out) {
    int i = blockIdx.x * blockDim.x + threadIdx.x;
    if (i < BB * TWO_D) out[i] = g_m[i];
}

// ---------------- launcher ----------------------------------------------------
extern "C" void kernel_launch(void* const* d_in, const int* in_sizes, int n_in,
                              void* d_out, int out_size) {
    const float* X     = (const float*)d_in[0];
    const float* mask  = (const float*)d_in[1];
    const float* fc_w  = (const float*)d_in[2];
    const float* fc_b  = (const float*)d_in[3];
    const float* w_im  = (const float*)d_in[4];
    const float* b_i   = (const float*)d_in[5];
    const float* w_fm  = (const float*)d_in[6];
    const float* b_f   = (const float*)d_in[7];
    const float* w_cm  = (const float*)d_in[8];
    const float* b_c   = (const float*)d_in[9];
    const float* w_om  = (const float*)d_in[10];
    const float* b_o   = (const float*)d_in[11];
    const float* m2q   = (const float*)d_in[12];
    const float* att_v = (const float*)d_in[13];
    float* out = (float*)d_out;

    float *p_hs, *p_query;
    __nv_bfloat16 *p_x_hi, *p_x_lo, *p_m_hi, *p_m_lo;
    __nv_bfloat16 *p_fc_hi, *p_fc_lo, *p_wg_hi, *p_wg_lo, *p_q_hi, *p_q_lo;
    cudaGetSymbolAddress((void**)&p_hs,    g_hs);
    cudaGetSymbolAddress((void**)&p_query, g_query);
    cudaGetSymbolAddress((void**)&p_x_hi,  g_x_hi);
    cudaGetSymbolAddress((void**)&p_x_lo,  g_x_lo);
    cudaGetSymbolAddress((void**)&p_m_hi,  g_m_hi);
    cudaGetSymbolAddress((void**)&p_m_lo,  g_m_lo);
    cudaGetSymbolAddress((void**)&p_fc_hi, g_fc_hi);
    cudaGetSymbolAddress((void**)&p_fc_lo, g_fc_lo);
    cudaGetSymbolAddress((void**)&p_wg_hi, g_wg_hi);
    cudaGetSymbolAddress((void**)&p_wg_lo, g_wg_lo);
    cudaGetSymbolAddress((void**)&p_q_hi,  g_q_hi);
    cudaGetSymbolAddress((void**)&p_q_lo,  g_q_lo);

    // proj 2-stage (OCC 2); gates/query 3-stage (still OCC 2)
    const int SM_PROJ  = (2 * 128 + 2 * 64) * 128 * 2;  // 98304  -> 2 CTAs/SM
    const int SM_GATE  = (2 * 64  + 2 * 64) * 128 * 3;  // 98304  -> 2 CTAs/SM
    const int SM_QUERY = (2 * 32  + 2 * 64) * 128 * 3;  // 73728  -> 2 CTAs/SM
    cudaFuncSetAttribute((const void*)mma_gemm_kernel<128, 64, 2, 4, false, 2, 2>,
                         cudaFuncAttributeMaxDynamicSharedMemorySize, SM_PROJ);
    cudaFuncSetAttribute((const void*)mma_gemm_kernel<64, 64, 2, 4, true, 2, 3>,
                         cudaFuncAttributeMaxDynamicSharedMemorySize, SM_GATE);
    cudaFuncSetAttribute((const void*)mma_gemm_kernel<32, 64, 2, 4, false, 2, 3>,
                         cudaFuncAttributeMaxDynamicSharedMemorySize, SM_QUERY);

    zero_mc_kernel<<<(BB * TWO_D + 255) / 256, 256>>>();
    conv_x_kernel<<<((int)((size_t)BB * NN * DD / 4) + 255) / 256, 256>>>(X);
    dim3 gfc(DD / 32, DD / 32);
    packT_kernel<<<gfc, 256>>>(fc_w, p_fc_hi, p_fc_lo, DD, DD, 1, 0);
    packT_kernel<<<gfc, 256>>>(m2q,  p_q_hi,  p_q_lo,  DD, DD, 1, 0);
    dim3 gg(DD / 32, TWO_D / 32);
    packT_kernel<<<gg, 256>>>(w_im, p_wg_hi, p_wg_lo, TWO_D, DD, 4, 0);

    // projection GEMM: hs = X @ fc_w + fc_b
    {
        dim3 grid(DD / 64, (BB * NN) / 128);
        mma_gemm_kernel<128, 64, 2, 4, false, 2, 2><<<grid, 256, SM_PROJ>>>(
            DD, p_x_hi, p_x_lo, DD, p_fc_hi, p_fc_lo, DD, p_hs, DD, fc_b,
            nullptr, nullptr, nullptr, nullptr);
    }

    // remaining gate packs
    packT_kernel<<<gg, 256>>>(w_fm, p_wg_hi, p_wg_lo, TWO_D, DD, 4, 1);
    packT_kernel<<<gg, 256>>>(w_cm, p_wg_hi, p_wg_lo, TWO_D, DD, 4, 2);
    packT_kernel<<<gg, 256>>>(w_om, p_wg_hi, p_wg_lo, TWO_D, DD, 4, 3);

    for (int step = 0; step < STEPS; step++) {
        // gates + fused combine: m[512,1024] @ Wg^T -> c, m_lstm (+hi/lo)
        {
            dim3 grid((4 * DD) / 64, BB / 64);
            mma_gemm_kernel<64, 64, 2, 4, true, 2, 3><<<grid, 256, SM_GATE>>>(
                TWO_D, p_m_hi, p_m_lo, TWO_D, p_wg_hi, p_wg_lo, TWO_D,
                nullptr, 0, nullptr, b_i, b_f, b_c, b_o);
        }
        // query = m_lstm @ m2q  (tiled HMMA GEMM, A = m_hi/lo[:, :512])
        {
            dim3 grid(DD / 64, BB / 32);
            mma_gemm_kernel<32, 64, 2, 4, false, 2, 3><<<grid, 256, SM_QUERY>>>(
                DD, p_m_hi, p_m_lo, TWO_D, p_q_hi, p_q_lo, DD,
                p_query, DD, nullptr, nullptr, nullptr, nullptr, nullptr);
        }
        attention_kernel<<<BB * HH, 128>>>(mask, att_v);
    }

    copy_out_kernel<<<(BB * TWO_D + 255) / 256, 256>>>(out);
}

// round 14
// speedup vs baseline: 1.0630x; 1.0152x over previous
#include <cuda_runtime.h>
#include <cuda_bf16.h>
#include <math.h>
#include <stdint.h>

// Problem constants
#define BB 512
#define NN 128
#define DD 512
#define HH 8
#define DH 64
#define TWO_D 1024
#define STEPS 6

#define SWZ(off) ((off) ^ (((off) >> 3) & 0x70))

// ---------------- PTX helpers (sm_80+ features only) ------------------------
__device__ __forceinline__ void cp_async16(uint32_t smem_addr, const void* gptr) {
    asm volatile("cp.async.cg.shared.global [%0], [%1], 16;\n"
                 :: "r"(smem_addr), "l"(gptr));
}
__device__ __forceinline__ void cp_commit() {
    asm volatile("cp.async.commit_group;\n" ::: "memory");
}
template<int N> __device__ __forceinline__ void cp_wait() {
    asm volatile("cp.async.wait_group %0;\n" :: "n"(N) : "memory");
}
__device__ __forceinline__ void ldsm_x4(uint32_t* r, uint32_t addr) {
    asm volatile("ldmatrix.sync.aligned.m8n8.x4.shared.b16 {%0,%1,%2,%3}, [%4];\n"
                 : "=r"(r[0]), "=r"(r[1]), "=r"(r[2]), "=r"(r[3]) : "r"(addr));
}
__device__ __forceinline__ void mma_16816(float* c, const uint32_t* a, const uint32_t* b) {
    asm volatile("mma.sync.aligned.m16n8k16.row.col.f32.bf16.bf16.f32 "
                 "{%0,%1,%2,%3}, {%4,%5,%6,%7}, {%8,%9}, {%0,%1,%2,%3};\n"
                 : "+f"(c[0]), "+f"(c[1]), "+f"(c[2]), "+f"(c[3])
                 : "r"(a[0]), "r"(a[1]), "r"(a[2]), "r"(a[3]), "r"(b[0]), "r"(b[1]));
}
__device__ __forceinline__ float tanh_fast(float x) {
    float y;
    asm("tanh.approx.f32 %0, %1;" : "=f"(y) : "f"(x));
    return y;
}

// ---------------- scratch (device globals) ----------------------------------
__device__ __align__(16) float g_hs[(size_t)BB * NN * DD];   // [B,N,D]
__device__ __align__(16) float g_c[BB * DD];                 // [B,D]
__device__ __align__(16) float g_query[BB * DD];             // [B,D]
__device__ __align__(16) float g_m1[DD];                     // step-1 m_lstm (batch-uniform)
__device__ __align__(16) float g_c1[DD];                     // step-1 cell (batch-uniform)
__device__ __align__(16) float g_qrow[DD];                   // step-1 query (batch-uniform)
// bf16 hi/lo operand copies
__device__ __align__(16) __nv_bfloat16 g_x_hi[(size_t)BB * NN * DD];
__device__ __align__(16) __nv_bfloat16 g_x_lo[(size_t)BB * NN * DD];
__device__ __align__(16) __nv_bfloat16 g_m_hi[BB * TWO_D];
__device__ __align__(16) __nv_bfloat16 g_m_lo[BB * TWO_D];
// packed transposed weights bf16 hi/lo
__device__ __align__(16) __nv_bfloat16 g_fc_hi[DD * DD];         // [N][K]
__device__ __align__(16) __nv_bfloat16 g_fc_lo[DD * DD];
__device__ __align__(16) __nv_bfloat16 g_wg_hi[4 * DD * TWO_D];  // [2048][1024], cols 4j+g
__device__ __align__(16) __nv_bfloat16 g_wg_lo[4 * DD * TWO_D];
__device__ __align__(16) __nv_bfloat16 g_q_hi[DD * DD];          // [N][K]
__device__ __align__(16) __nv_bfloat16 g_q_lo[DD * DD];

__device__ __forceinline__ float sigmoidf_(float x) { return 1.0f / (1.0f + expf(-x)); }

// ---------------- tile copy: gmem bf16 [rows][ld] -> smem SW128 -------------
template<int ROWS>
__device__ __forceinline__ void copy_tile(uint32_t sbase, const __nv_bfloat16* __restrict__ g,
                                          int ldg, int r0, int k0, int t) {
#pragma unroll
    for (int v = t; v < ROWS * 8; v += 256) {
        int row = v >> 3, ch = v & 7;
        uint32_t off = SWZ((uint32_t)(row * 128 + ch * 16));
        cp_async16(sbase + off, g + (size_t)(r0 + row) * ldg + k0 + ch * 8);
    }
}

// ---------------- bf16-split HMMA GEMM --------------------------------------
// C[M,N] = (Ahi+Alo)[M,K] @ (Bhi+Blo)^T, B stored [N][K]. 3-term split, fp32 acc.
// STG=2: double buffer. STG=3: ring, 1 barrier/K-block.
// FUSE=true: gate path — cols interleaved 4j+g; epilogue does the LSTM combine;
//            mdst (if non-null) receives m_lstm fp32 at [row*TWO_D + jj].
template<int BM, int BN, int WM, int WN, bool FUSE, int OCC, int STG>
__global__ void __launch_bounds__(256, OCC)
mma_gemm_kernel(int K,
                const __nv_bfloat16* __restrict__ Ahi, const __nv_bfloat16* __restrict__ Alo, int lda,
                const __nv_bfloat16* __restrict__ Bhi, const __nv_bfloat16* __restrict__ Blo, int ldb,
                float* __restrict__ C, int ldc, const float* __restrict__ bias,
                const float* __restrict__ bi, const float* __restrict__ bf,
                const float* __restrict__ bc, const float* __restrict__ bo,
                float* __restrict__ mdst)
{
    constexpr int WTM = BM / WM, WTN = BN / WN;
    constexpr int MT = WTM / 16, NT = WTN / 8, NP = NT / 2;
    constexpr int STAGE = (2 * BM + 2 * BN) * 128;
    static_assert(WM * WN == 8 && MT >= 1 && NP >= 1, "cfg");
    static_assert(STG == 2 || STG == 3, "stages");

    extern __shared__ char smem[];
    const int t = threadIdx.x, lane = t & 31, wid = t >> 5;
    const int wm = wid % WM, wn = wid / WM;
    const int m0 = blockIdx.y * BM, n0 = blockIdx.x * BN;
    const uint32_t sbase = (uint32_t)__cvta_generic_to_shared(smem);

    float c[MT][NT][4];
#pragma unroll
    for (int i = 0; i < MT; i++)
#pragma unroll
        for (int j = 0; j < NT; j++)
#pragma unroll
            for (int q = 0; q < 4; q++) c[i][j][q] = 0.0f;

    const int NB = K >> 6;

    auto issue = [&](int kb, int buf) {
        uint32_t st = sbase + (uint32_t)buf * STAGE;
        copy_tile<BM>(st,                           Ahi, lda, m0, kb * 64, t);
        copy_tile<BM>(st + BM * 128,                Alo, lda, m0, kb * 64, t);
        copy_tile<BN>(st + 2 * BM * 128,            Bhi, ldb, n0, kb * 64, t);
        copy_tile<BN>(st + 2 * BM * 128 + BN * 128, Blo, ldb, n0, kb * 64, t);
        cp_commit();
    };

    auto compute_block = [&](uint32_t st) {
        const uint32_t aHi = st, aLo = st + BM * 128;
        const uint32_t bHi = st + 2 * BM * 128, bLo = bHi + BN * 128;
#pragma unroll
        for (int s = 0; s < 4; s++) {
            uint32_t ahf[MT][4], alf[MT][4];
            const int      arow  = wm * WTM + (lane & 15);
            const uint32_t abyte = s * 32 + ((lane >> 4) << 4);
#pragma unroll
            for (int i = 0; i < MT; i++) {
                uint32_t off = SWZ((uint32_t)((arow + i * 16) * 128) + abyte);
                ldsm_x4(ahf[i], aHi + off);
                ldsm_x4(alf[i], aLo + off);
            }
            uint32_t bhf[NP][4], blf[NP][4];
            const int      brow  = wn * WTN + ((lane >> 4) << 3) + (lane & 7);
            const uint32_t bbyte = s * 32 + (((lane >> 3) & 1) << 4);
#pragma unroll
            for (int p = 0; p < NP; p++) {
                uint32_t off = SWZ((uint32_t)((brow + p * 16) * 128) + bbyte);
                ldsm_x4(bhf[p], bHi + off);
                ldsm_x4(blf[p], bLo + off);
            }
#pragma unroll
            for (int i = 0; i < MT; i++)
#pragma unroll
                for (int j = 0; j < NT; j++) {
                    const uint32_t* bh = &bhf[j >> 1][(j & 1) * 2];
                    const uint32_t* bl = &blf[j >> 1][(j & 1) * 2];
                    mma_16816(c[i][j], ahf[i], bh);
                    mma_16816(c[i][j], ahf[i], bl);
                    mma_16816(c[i][j], alf[i], bh);
                }
        }
    };

    issue(0, 0);
    issue(1, 1);

    if constexpr (STG == 2) {
        for (int kb = 0; kb < NB; kb++) {
            if (kb + 1 < NB) cp_wait<1>(); else cp_wait<0>();
            __syncthreads();
            compute_block(sbase + (uint32_t)(kb & 1) * STAGE);
            __syncthreads();
            if (kb + 2 < NB) issue(kb + 2, kb & 1);
        }
    } else {
        for (int kb = 0; kb < NB; kb++) {
            if (kb + 1 < NB) cp_wait<1>(); else cp_wait<0>();
            __syncthreads();
            if (kb + 2 < NB) issue(kb + 2, (kb + 2) % 3);
            compute_block(sbase + (uint32_t)(kb % 3) * STAGE);
        }
    }

    const int wr = m0 + wm * WTM, wc = n0 + wn * WTN;
    if constexpr (FUSE) {
        const int q = lane & 3;
        const bool odd = (q & 1) != 0;
#pragma unroll
        for (int i = 0; i < MT; i++) {
            const int r = wr + i * 16 + (lane >> 2);
#pragma unroll
            for (int j = 0; j < NT; j++) {
                const int Gc = wc + j * 8 + q * 2;
                const int jj = Gc >> 2;
                float v0 = c[i][j][0], v1 = c[i][j][1];
                float v2 = c[i][j][2], v3 = c[i][j][3];
                if (!odd) { v0 += bi[jj]; v1 += bf[jj]; v2 += bi[jj]; v3 += bf[jj]; }
                else      { v0 += bc[jj]; v1 += bo[jj]; v2 += bc[jj]; v3 += bo[jj]; }
                float u0 = __shfl_xor_sync(0xFFFFFFFF, v0, 1);
                float u1 = __shfl_xor_sync(0xFFFFFFFF, v1, 1);
                float u2 = __shfl_xor_sync(0xFFFFFFFF, v2, 1);
                float u3 = __shfl_xor_sync(0xFFFFFFFF, v3, 1);
                const int row = odd ? (r + 8) : r;
                const float ip_ = odd ? u2 : v0;
                const float fp_ = odd ? u3 : v1;
                const float cp_ = odd ? v2 : u0;
                const float op_ = odd ? v3 : u1;
                const float cold = g_c[row * DD + jj];
                const float cn = sigmoidf_(fp_) * cold + sigmoidf_(ip_) * tanhf(cp_);
                g_c[row * DD + jj] = cn;
                const float mv = sigmoidf_(op_) * tanhf(cn);
                if (mdst) mdst[row * TWO_D + jj] = mv;
                const __nv_bfloat16 h = __float2bfloat16_rn(mv);
                g_m_hi[row * TWO_D + jj] = h;
                g_m_lo[row * TWO_D + jj] = __float2bfloat16_rn(mv - __bfloat162float(h));
            }
        }
    } else {
#pragma unroll
        for (int i = 0; i < MT; i++) {
            int r0 = wr + i * 16 + (lane >> 2);
#pragma unroll
            for (int j = 0; j < NT; j++) {
                int col = wc + j * 8 + (lane & 3) * 2;
                float bx = 0.0f, by = 0.0f;
                if (bias) { bx = bias[col]; by = bias[col + 1]; }
                float2 v0 = make_float2(c[i][j][0] + bx, c[i][j][1] + by);
                float2 v1 = make_float2(c[i][j][2] + bx, c[i][j][3] + by);
                *(float2*)&C[(size_t)r0 * ldc + col]       = v0;
                *(float2*)&C[(size_t)(r0 + 8) * ldc + col] = v1;
            }
        }
    }
}

// ---------------- conversion / pack kernels ---------------------------------
__global__ void conv_x_kernel(const float* __restrict__ X) {
    int i = blockIdx.x * blockDim.x + threadIdx.x;
    const int n4 = (int)((size_t)BB * NN * DD / 4);
    if (i >= n4) return;
    float4 x = ((const float4*)X)[i];
    __nv_bfloat16 h0 = __float2bfloat16_rn(x.x), h1 = __float2bfloat16_rn(x.y);
    __nv_bfloat16 h2 = __float2bfloat16_rn(x.z), h3 = __float2bfloat16_rn(x.w);
    __nv_bfloat162 hh0(h0, h1), hh1(h2, h3);
    __nv_bfloat162 ll0(__float2bfloat16_rn(x.x - __bfloat162float(h0)),
                       __float2bfloat16_rn(x.y - __bfloat162float(h1)));
    __nv_bfloat162 ll1(__float2bfloat16_rn(x.z - __bfloat162float(h2)),
                       __float2bfloat16_rn(x.w - __bfloat162float(h3)));
    ((uint2*)g_x_hi)[i] = make_uint2(*(uint32_t*)&hh0, *(uint32_t*)&hh1);
    ((uint2*)g_x_lo)[i] = make_uint2(*(uint32_t*)&ll0, *(uint32_t*)&ll1);
}

// tiled transpose pack: w[K][N] -> out_hi/lo rows (n*rowMul+rowOff), cols k
__global__ void packT_kernel(const float* __restrict__ w,
                             __nv_bfloat16* __restrict__ hi, __nv_bfloat16* __restrict__ lo,
                             int K, int N, int rowMul, int rowOff) {
    __shared__ float s[32][33];
    const int n0 = blockIdx.x * 32, k0 = blockIdx.y * 32;
    const int tx = threadIdx.x & 31, ty = threadIdx.x >> 5;   // 32 x 8
#pragma unroll
    for (int i = 0; i < 4; i++) {
        int k = k0 + ty + i * 8;
        s[ty + i * 8][tx] = w[(size_t)k * N + n0 + tx];
    }
    __syncthreads();
#pragma unroll
    for (int i = 0; i < 4; i++) {
        int n = n0 + ty + i * 8;
        float x = s[tx][ty + i * 8];
        __nv_bfloat16 h = __float2bfloat16_rn(x);
        size_t o = (size_t)(n * rowMul + rowOff) * K + k0 + tx;
        hi[o] = h;
        lo[o] = __float2bfloat16_rn(x - __bfloat162float(h));
    }
}

// ---------------- step-1 analytic shortcut -----------------------------------
// m=0, c=0 => gates are bias-only and batch-independent. One block, 512 threads.
__global__ void init_step1_kernel(const float* __restrict__ bi, const float* __restrict__ bf,
                                  const float* __restrict__ bc, const float* __restrict__ bo,
                                  const float* __restrict__ m2q) {
    __shared__ float m1s[DD];
    const int j = threadIdx.x;    // 512
    const float c1 = sigmoidf_(bi[j]) * tanhf(bc[j]);
    const float m1 = sigmoidf_(bo[j]) * tanhf(c1);
    g_c1[j] = c1;
    g_m1[j] = m1;
    m1s[j] = m1;
    __syncthreads();
    // qrow[j] = sum_k m1[k] * m2q[k][j]   (coalesced across j)
    float acc = 0.0f;
    for (int k = 0; k < DD; k++) acc += m1s[k] * m2q[k * DD + j];
    g_qrow[j] = acc;
}

// broadcast step-1 state to all batches: c, m_hi/lo (m_lstm half), query
__global__ void bcast_step1_kernel() {
    const int b = blockIdx.x;     // 512
    const int j = threadIdx.x;    // 512
    const float m1 = g_m1[j];
    g_c[b * DD + j] = g_c1[j];
    const __nv_bfloat16 h = __float2bfloat16_rn(m1);
    g_m_hi[b * TWO_D + j] = h;
    g_m_lo[b * TWO_D + j] = __float2bfloat16_rn(m1 - __bfloat162float(h));
    g_query[b * DD + j] = g_qrow[j];
}

// ---------------- attention ---------------------------------------------------
// energies -> softmax -> read (query from g_query), MUFU tanh in energies.
// mdst (if non-null) receives read fp32 at [b*TWO_D + DD + h*DH + t].
__global__ void __launch_bounds__(128)
attention_kernel(const float* __restrict__ mask, const float* __restrict__ att_v,
                 float* __restrict__ mdst) {
    __shared__ float hs_s[NN][DH + 1];
    __shared__ float qv[DH];
    __shared__ float av[DH];
    __shared__ float red[NN];
    __shared__ float attn[NN];

    const int t = threadIdx.x;
    const int b = blockIdx.x >> 3;
    const int h = blockIdx.x & 7;

    const float* hs_base = g_hs + (size_t)b * NN * DD + h * DH;
    for (int i = t; i < NN * DH; i += 128) {
        int n = i >> 6, d = i & 63;
        hs_s[n][d] = hs_base[(size_t)n * DD + d];
    }
    if (t < DH) {
        qv[t] = g_query[b * DD + h * DH + t];
        av[t] = att_v[h * DH + t];
    }
    __syncthreads();

    float e = 0.0f;
#pragma unroll 8
    for (int d = 0; d < DH; d++) e += tanh_fast(qv[d] + hs_s[t][d]) * av[d];
    e += (1.0f - mask[b * NN + t]) * (-1e10f);

    red[t] = e;
    __syncthreads();
#pragma unroll
    for (int s = 64; s > 0; s >>= 1) {
        if (t < s) red[t] = fmaxf(red[t], red[t + s]);
        __syncthreads();
    }
    const float mx = red[0];
    __syncthreads();

    float p = expf(e - mx);
    attn[t] = p; red[t] = p;
    __syncthreads();
#pragma unroll
    for (int s = 64; s > 0; s >>= 1) {
        if (t < s) red[t] += red[t + s];
        __syncthreads();
    }
    const float inv_sum = 1.0f / red[0];
    __syncthreads();
    attn[t] *= inv_sum;
    __syncthreads();

    if (t < DH) {
        float r = 0.0f;
#pragma unroll 8
        for (int n = 0; n < NN; n++) r += attn[n] * hs_s[n][t];
        int col = DD + h * DH + t;
        if (mdst) mdst[b * TWO_D + col] = r;
        __nv_bfloat16 hh = __float2bfloat16_rn(r);
        g_m_hi[b * TWO_D + col] = hh;
        g_m_lo[b * TWO_D + col] = __float2bfloat16_rn(r - __bfloat162float(hh));
    }
}

// ---------------- launcher ----------------------------------------------------
extern "C" void kernel_launch(void* const* d_in, const int* in_sizes, int n_in,
                              void* d_out, int out_size) {
    const float* X     = (const float*)d_in[0];
    const float* mask  = (const float*)d_in[1];
    const float* fc_w  = (const float*)d_in[2];
    const float* fc_b  = (const float*)d_in[3];
    const float* w_im  = (const float*)d_in[4];
    const float* b_i   = (const float*)d_in[5];
    const float* w_fm  = (const float*)d_in[6];
    const float* b_f   = (const float*)d_in[7];
    const float* w_cm  = (const float*)d_in[8];
    const float* b_c   = (const float*)d_in[9];
    const float* w_om  = (const float*)d_in[10];
    const float* b_o   = (const float*)d_in[11];
    const float* m2q   = (const float*)d_in[12];
    const float* att_v = (const float*)d_in[13];
    float* out = (float*)d_out;

    float *p_hs, *p_query;
    __nv_bfloat16 *p_x_hi, *p_x_lo, *p_m_hi, *p_m_lo;
    __nv_bfloat16 *p_fc_hi, *p_fc_lo, *p_wg_hi, *p_wg_lo, *p_q_hi, *p_q_lo;
    cudaGetSymbolAddress((void**)&p_hs,    g_hs);
    cudaGetSymbolAddress((void**)&p_query, g_query);
    cudaGetSymbolAddress((void**)&p_x_hi,  g_x_hi);
    cudaGetSymbolAddress((void**)&p_x_lo,  g_x_lo);
    cudaGetSymbolAddress((void**)&p_m_hi,  g_m_hi);
    cudaGetSymbolAddress((void**)&p_m_lo,  g_m_lo);
    cudaGetSymbolAddress((void**)&p_fc_hi, g_fc_hi);
    cudaGetSymbolAddress((void**)&p_fc_lo, g_fc_lo);
    cudaGetSymbolAddress((void**)&p_wg_hi, g_wg_hi);
    cudaGetSymbolAddress((void**)&p_wg_lo, g_wg_lo);
    cudaGetSymbolAddress((void**)&p_q_hi,  g_q_hi);
    cudaGetSymbolAddress((void**)&p_q_lo,  g_q_lo);

    const int SM_PROJ  = (2 * 128 + 2 * 64) * 128 * 2;  // 98304  -> 2 CTAs/SM
    const int SM_GATE  = (2 * 64  + 2 * 64) * 128 * 3;  // 98304  -> 2 CTAs/SM
    const int SM_QUERY = (2 * 32  + 2 * 64) * 128 * 3;  // 73728  -> 2 CTAs/SM
    cudaFuncSetAttribute((const void*)mma_gemm_kernel<128, 64, 2, 4, false, 2, 2>,
                         cudaFuncAttributeMaxDynamicSharedMemorySize, SM_PROJ);
    cudaFuncSetAttribute((const void*)mma_gemm_kernel<64, 64, 2, 4, true, 2, 3>,
                         cudaFuncAttributeMaxDynamicSharedMemorySize, SM_GATE);
    cudaFuncSetAttribute((const void*)mma_gemm_kernel<32, 64, 2, 4, false, 2, 3>,
                         cudaFuncAttributeMaxDynamicSharedMemorySize, SM_QUERY);

    // my launches 1-3; harness prepends 2, so my #4 (proj) = profiled slot 6
    conv_x_kernel<<<((int)((size_t)BB * NN * DD / 4) + 255) / 256, 256>>>(X);
    dim3 gfc(DD / 32, DD / 32);
    packT_kernel<<<gfc, 256>>>(fc_w, p_fc_hi, p_fc_lo, DD, DD, 1, 0);
    init_step1_kernel<<<1, DD>>>(b_i, b_f, b_c, b_o, m2q);

    // launch #4: projection GEMM (profiled): hs = X @ fc_w + fc_b
    {
        dim3 grid(DD / 64, (BB * NN) / 128);
        mma_gemm_kernel<128, 64, 2, 4, false, 2, 2><<<grid, 256, SM_PROJ>>>(
            DD, p_x_hi, p_x_lo, DD, p_fc_hi, p_fc_lo, DD, p_hs, DD, fc_b,
            nullptr, nullptr, nullptr, nullptr, nullptr);
    }

    // step-1 state broadcast + remaining packs
    bcast_step1_kernel<<<BB, DD>>>();
    packT_kernel<<<gfc, 256>>>(m2q, p_q_hi, p_q_lo, DD, DD, 1, 0);
    dim3 gg(DD / 32, TWO_D / 32);
    packT_kernel<<<gg, 256>>>(w_im, p_wg_hi, p_wg_lo, TWO_D, DD, 4, 0);
    packT_kernel<<<gg, 256>>>(w_fm, p_wg_hi, p_wg_lo, TWO_D, DD, 4, 1);
    packT_kernel<<<gg, 256>>>(w_cm, p_wg_hi, p_wg_lo, TWO_D, DD, 4, 2);
    packT_kernel<<<gg, 256>>>(w_om, p_wg_hi, p_wg_lo, TWO_D, DD, 4, 3);

    // step 1: attention only (gates/query replaced by analytic shortcut)
    attention_kernel<<<BB * HH, 128>>>(mask, att_v, nullptr);

    // steps 2..6
    for (int step = 0; step < STEPS - 1; step++) {
        const bool last = (step == STEPS - 2);
        {
            dim3 grid((4 * DD) / 64, BB / 64);
            mma_gemm_kernel<64, 64, 2, 4, true, 2, 3><<<grid, 256, SM_GATE>>>(
                TWO_D, p_m_hi, p_m_lo, TWO_D, p_wg_hi, p_wg_lo, TWO_D,
                nullptr, 0, nullptr, b_i, b_f, b_c, b_o, last ? out : nullptr);
        }
        {
            dim3 grid(DD / 64, BB / 32);
            mma_gemm_kernel<32, 64, 2, 4, false, 2, 3><<<grid, 256, SM_QUERY>>>(
                DD, p_m_hi, p_m_lo, TWO_D, p_q_hi, p_q_lo, DD,
                p_query, DD, nullptr, nullptr, nullptr, nullptr, nullptr, nullptr);
        }
        attention_kernel<<<BB * HH, 128>>>(mask, att_v, last ? out : nullptr);
    }
}

// round 15
// speedup vs baseline: 1.1664x; 1.0973x over previous
#include <cuda_runtime.h>
#include <cuda_fp16.h>
#include <math.h>
#include <stdint.h>

// Problem constants
#define BB 512
#define NN 128
#define DD 512
#define HH 8
#define DH 64
#define TWO_D 1024
#define STEPS 6

#define SWZ(off) ((off) ^ (((off) >> 3) & 0x70))

// ---------------- PTX helpers (sm_80+ features only) ------------------------
__device__ __forceinline__ void cp_async16(uint32_t smem_addr, const void* gptr) {
    asm volatile("cp.async.cg.shared.global [%0], [%1], 16;\n"
                 :: "r"(smem_addr), "l"(gptr));
}
__device__ __forceinline__ void cp_commit() {
    asm volatile("cp.async.commit_group;\n" ::: "memory");
}
template<int N> __device__ __forceinline__ void cp_wait() {
    asm volatile("cp.async.wait_group %0;\n" :: "n"(N) : "memory");
}
__device__ __forceinline__ void ldsm_x4(uint32_t* r, uint32_t addr) {
    asm volatile("ldmatrix.sync.aligned.m8n8.x4.shared.b16 {%0,%1,%2,%3}, [%4];\n"
                 : "=r"(r[0]), "=r"(r[1]), "=r"(r[2]), "=r"(r[3]) : "r"(addr));
}
__device__ __forceinline__ void mma_16816_f16(float* c, const uint32_t* a, const uint32_t* b) {
    asm volatile("mma.sync.aligned.m16n8k16.row.col.f32.f16.f16.f32 "
                 "{%0,%1,%2,%3}, {%4,%5,%6,%7}, {%8,%9}, {%0,%1,%2,%3};\n"
                 : "+f"(c[0]), "+f"(c[1]), "+f"(c[2]), "+f"(c[3])
                 : "r"(a[0]), "r"(a[1]), "r"(a[2]), "r"(a[3]), "r"(b[0]), "r"(b[1]));
}
__device__ __forceinline__ float tanh_fast(float x) {
    float y;
    asm("tanh.approx.f32 %0, %1;" : "=f"(y) : "f"(x));
    return y;
}

// ---------------- scratch (device globals) ----------------------------------
__device__ __align__(16) float g_hs[(size_t)BB * NN * DD];   // [B,N,D]
__device__ __align__(16) float g_c[BB * DD];                 // [B,D]
__device__ __align__(16) float g_query[BB * DD];             // [B,D]
__device__ __align__(16) float g_m1[DD];                     // step-1 m_lstm (uniform)
__device__ __align__(16) float g_c1[DD];                     // step-1 cell (uniform)
__device__ __align__(16) float g_qrow[DD];                   // step-1 query (uniform)
// fp16 hi/lo A-side operands
__device__ __align__(16) __half g_x_hi[(size_t)BB * NN * DD];
__device__ __align__(16) __half g_x_lo[(size_t)BB * NN * DD];
__device__ __align__(16) __half g_m_hi[BB * TWO_D];
__device__ __align__(16) __half g_m_lo[BB * TWO_D];
// fp16 single-precision B-side weights (transposed [N][K])
__device__ __align__(16) __half g_fc_h[DD * DD];
__device__ __align__(16) __half g_wg_h[4 * DD * TWO_D];   // [2048][1024], cols 4j+g
__device__ __align__(16) __half g_q_h[DD * DD];

__device__ __forceinline__ float sigmoidf_(float x) { return 1.0f / (1.0f + expf(-x)); }

// ---------------- tile copy: gmem b16 [rows][ld] -> smem SW128 ---------------
template<int ROWS>
__device__ __forceinline__ void copy_tile(uint32_t sbase, const __half* __restrict__ g,
                                          int ldg, int r0, int k0, int t) {
#pragma unroll
    for (int v = t; v < ROWS * 8; v += 256) {
        int row = v >> 3, ch = v & 7;
        uint32_t off = SWZ((uint32_t)(row * 128 + ch * 16));
        cp_async16(sbase + off, g + (size_t)(r0 + row) * ldg + k0 + ch * 8);
    }
}

// ---------------- fp16 A-split HMMA GEMM -------------------------------------
// C[M,N] = (Ahi+Alo)[M,K] @ Bh^T, B stored [N][K] fp16. 2-term, fp32 acc.
// STG=2: double buffer. STG=3: ring, 1 barrier/K-block.
// FUSE=true: gate path — cols interleaved 4j+g; epilogue does the LSTM combine;
//            mdst (if non-null) receives m_lstm fp32 at [row*TWO_D + jj].
template<int BM, int BN, int WM, int WN, bool FUSE, int OCC, int STG>
__global__ void __launch_bounds__(256, OCC)
mma_gemm_kernel(int K,
                const __half* __restrict__ Ahi, const __half* __restrict__ Alo, int lda,
                const __half* __restrict__ Bh, int ldb,
                float* __restrict__ C, int ldc, const float* __restrict__ bias,
                const float* __restrict__ bi, const float* __restrict__ bf,
                const float* __restrict__ bc, const float* __restrict__ bo,
                float* __restrict__ mdst)
{
    constexpr int WTM = BM / WM, WTN = BN / WN;
    constexpr int MT = WTM / 16, NT = WTN / 8, NP = NT / 2;
    constexpr int STAGE = (2 * BM + BN) * 128;
    static_assert(WM * WN == 8 && MT >= 1 && NP >= 1, "cfg");
    static_assert(STG == 2 || STG == 3, "stages");

    extern __shared__ char smem[];
    const int t = threadIdx.x, lane = t & 31, wid = t >> 5;
    const int wm = wid % WM, wn = wid / WM;
    const int m0 = blockIdx.y * BM, n0 = blockIdx.x * BN;
    const uint32_t sbase = (uint32_t)__cvta_generic_to_shared(smem);

    float c[MT][NT][4];
#pragma unroll
    for (int i = 0; i < MT; i++)
#pragma unroll
        for (int j = 0; j < NT; j++)
#pragma unroll
            for (int q = 0; q < 4; q++) c[i][j][q] = 0.0f;

    const int NB = K >> 6;

    auto issue = [&](int kb, int buf) {
        uint32_t st = sbase + (uint32_t)buf * STAGE;
        copy_tile<BM>(st,                Ahi, lda, m0, kb * 64, t);
        copy_tile<BM>(st + BM * 128,     Alo, lda, m0, kb * 64, t);
        copy_tile<BN>(st + 2 * BM * 128, Bh,  ldb, n0, kb * 64, t);
        cp_commit();
    };

    auto compute_block = [&](uint32_t st) {
        const uint32_t aHi = st, aLo = st + BM * 128;
        const uint32_t bH = st + 2 * BM * 128;
#pragma unroll
        for (int s = 0; s < 4; s++) {
            uint32_t ahf[MT][4], alf[MT][4];
            const int      arow  = wm * WTM + (lane & 15);
            const uint32_t abyte = s * 32 + ((lane >> 4) << 4);
#pragma unroll
            for (int i = 0; i < MT; i++) {
                uint32_t off = SWZ((uint32_t)((arow + i * 16) * 128) + abyte);
                ldsm_x4(ahf[i], aHi + off);
                ldsm_x4(alf[i], aLo + off);
            }
            uint32_t bhf[NP][4];
            const int      brow  = wn * WTN + ((lane >> 4) << 3) + (lane & 7);
            const uint32_t bbyte = s * 32 + (((lane >> 3) & 1) << 4);
#pragma unroll
            for (int p = 0; p < NP; p++) {
                uint32_t off = SWZ((uint32_t)((brow + p * 16) * 128) + bbyte);
                ldsm_x4(bhf[p], bH + off);
            }
#pragma unroll
            for (int i = 0; i < MT; i++)
#pragma unroll
                for (int j = 0; j < NT; j++) {
                    const uint32_t* bh = &bhf[j >> 1][(j & 1) * 2];
                    mma_16816_f16(c[i][j], ahf[i], bh);
                    mma_16816_f16(c[i][j], alf[i], bh);
                }
        }
    };

    issue(0, 0);
    issue(1, 1);

    if constexpr (STG == 2) {
        for (int kb = 0; kb < NB; kb++) {
            if (kb + 1 < NB) cp_wait<1>(); else cp_wait<0>();
            __syncthreads();
            compute_block(sbase + (uint32_t)(kb & 1) * STAGE);
            __syncthreads();
            if (kb + 2 < NB) issue(kb + 2, kb & 1);
        }
    } else {
        for (int kb = 0; kb < NB; kb++) {
            if (kb + 1 < NB) cp_wait<1>(); else cp_wait<0>();
            __syncthreads();
            if (kb + 2 < NB) issue(kb + 2, (kb + 2) % 3);
            compute_block(sbase + (uint32_t)(kb % 3) * STAGE);
        }
    }

    const int wr = m0 + wm * WTM, wc = n0 + wn * WTN;
    if constexpr (FUSE) {
        const int q = lane & 3;
        const bool odd = (q & 1) != 0;
#pragma unroll
        for (int i = 0; i < MT; i++) {
            const int r = wr + i * 16 + (lane >> 2);
#pragma unroll
            for (int j = 0; j < NT; j++) {
                const int Gc = wc + j * 8 + q * 2;
                const int jj = Gc >> 2;
                float v0 = c[i][j][0], v1 = c[i][j][1];
                float v2 = c[i][j][2], v3 = c[i][j][3];
                if (!odd) { v0 += bi[jj]; v1 += bf[jj]; v2 += bi[jj]; v3 += bf[jj]; }
                else      { v0 += bc[jj]; v1 += bo[jj]; v2 += bc[jj]; v3 += bo[jj]; }
                float u0 = __shfl_xor_sync(0xFFFFFFFF, v0, 1);
                float u1 = __shfl_xor_sync(0xFFFFFFFF, v1, 1);
                float u2 = __shfl_xor_sync(0xFFFFFFFF, v2, 1);
                float u3 = __shfl_xor_sync(0xFFFFFFFF, v3, 1);
                const int row = odd ? (r + 8) : r;
                const float ip_ = odd ? u2 : v0;
                const float fp_ = odd ? u3 : v1;
                const float cp_ = odd ? v2 : u0;
                const float op_ = odd ? v3 : u1;
                const float cold = g_c[row * DD + jj];
                const float cn = sigmoidf_(fp_) * cold + sigmoidf_(ip_) * tanhf(cp_);
                g_c[row * DD + jj] = cn;
                const float mv = sigmoidf_(op_) * tanhf(cn);
                if (mdst) mdst[row * TWO_D + jj] = mv;
                const __half h = __float2half_rn(mv);
                g_m_hi[row * TWO_D + jj] = h;
                g_m_lo[row * TWO_D + jj] = __float2half_rn(mv - __half2float(h));
            }
        }
    } else {
#pragma unroll
        for (int i = 0; i < MT; i++) {
            int r0 = wr + i * 16 + (lane >> 2);
#pragma unroll
            for (int j = 0; j < NT; j++) {
                int col = wc + j * 8 + (lane & 3) * 2;
                float bx = 0.0f, by = 0.0f;
                if (bias) { bx = bias[col]; by = bias[col + 1]; }
                float2 v0 = make_float2(c[i][j][0] + bx, c[i][j][1] + by);
                float2 v1 = make_float2(c[i][j][2] + bx, c[i][j][3] + by);
                *(float2*)&C[(size_t)r0 * ldc + col]       = v0;
                *(float2*)&C[(size_t)(r0 + 8) * ldc + col] = v1;
            }
        }
    }
}

// ---------------- conversion / pack kernels ---------------------------------
__global__ void conv_x_kernel(const float* __restrict__ X) {
    int i = blockIdx.x * blockDim.x + threadIdx.x;
    const int n4 = (int)((size_t)BB * NN * DD / 4);
    if (i >= n4) return;
    float4 x = ((const float4*)X)[i];
    __half h0 = __float2half_rn(x.x), h1 = __float2half_rn(x.y);
    __half h2 = __float2half_rn(x.z), h3 = __float2half_rn(x.w);
    __half2 hh0(h0, h1), hh1(h2, h3);
    __half2 ll0(__float2half_rn(x.x - __half2float(h0)),
                __float2half_rn(x.y - __half2float(h1)));
    __half2 ll1(__float2half_rn(x.z - __half2float(h2)),
                __float2half_rn(x.w - __half2float(h3)));
    ((uint2*)g_x_hi)[i] = make_uint2(*(uint32_t*)&hh0, *(uint32_t*)&hh1);
    ((uint2*)g_x_lo)[i] = make_uint2(*(uint32_t*)&ll0, *(uint32_t*)&ll1);
}

// tiled transpose pack: w[K][N] -> out rows (n*rowMul+rowOff), cols k, fp16
__global__ void packT_kernel(const float* __restrict__ w, __half* __restrict__ dst,
                             int K, int N, int rowMul, int rowOff) {
    __shared__ float s[32][33];
    const int n0 = blockIdx.x * 32, k0 = blockIdx.y * 32;
    const int tx = threadIdx.x & 31, ty = threadIdx.x >> 5;   // 32 x 8
#pragma unroll
    for (int i = 0; i < 4; i++) {
        int k = k0 + ty + i * 8;
        s[ty + i * 8][tx] = w[(size_t)k * N + n0 + tx];
    }
    __syncthreads();
#pragma unroll
    for (int i = 0; i < 4; i++) {
        int n = n0 + ty + i * 8;
        dst[(size_t)(n * rowMul + rowOff) * K + k0 + tx] = __float2half_rn(s[tx][ty + i * 8]);
    }
}

// ---------------- step-1 analytic shortcut -----------------------------------
__global__ void init_step1_kernel(const float* __restrict__ bi, const float* __restrict__ bf,
                                  const float* __restrict__ bc, const float* __restrict__ bo,
                                  const float* __restrict__ m2q) {
    __shared__ float m1s[DD];
    const int j = threadIdx.x;    // 512
    const float c1 = sigmoidf_(bi[j]) * tanhf(bc[j]);
    const float m1 = sigmoidf_(bo[j]) * tanhf(c1);
    g_c1[j] = c1;
    g_m1[j] = m1;
    m1s[j] = m1;
    __syncthreads();
    float acc = 0.0f;
    for (int k = 0; k < DD; k++) acc += m1s[k] * m2q[k * DD + j];
    g_qrow[j] = acc;
}

__global__ void bcast_step1_kernel() {
    const int b = blockIdx.x;     // 512
    const int j = threadIdx.x;    // 512
    const float m1 = g_m1[j];
    g_c[b * DD + j] = g_c1[j];
    const __half h = __float2half_rn(m1);
    g_m_hi[b * TWO_D + j] = h;
    g_m_lo[b * TWO_D + j] = __float2half_rn(m1 - __half2float(h));
    g_query[b * DD + j] = g_qrow[j];
}

// ---------------- attention ---------------------------------------------------
__global__ void __launch_bounds__(128)
attention_kernel(const float* __restrict__ mask, const float* __restrict__ att_v,
                 float* __restrict__ mdst) {
    __shared__ float hs_s[NN][DH + 1];
    __shared__ float qv[DH];
    __shared__ float av[DH];
    __shared__ float red[NN];
    __shared__ float attn[NN];

    const int t = threadIdx.x;
    const int b = blockIdx.x >> 3;
    const int h = blockIdx.x & 7;

    const float* hs_base = g_hs + (size_t)b * NN * DD + h * DH;
    for (int i = t; i < NN * DH; i += 128) {
        int n = i >> 6, d = i & 63;
        hs_s[n][d] = hs_base[(size_t)n * DD + d];
    }
    if (t < DH) {
        qv[t] = g_query[b * DD + h * DH + t];
        av[t] = att_v[h * DH + t];
    }
    __syncthreads();

    float e = 0.0f;
#pragma unroll 8
    for (int d = 0; d < DH; d++) e += tanh_fast(qv[d] + hs_s[t][d]) * av[d];
    e += (1.0f - mask[b * NN + t]) * (-1e10f);

    red[t] = e;
    __syncthreads();
#pragma unroll
    for (int s = 64; s > 0; s >>= 1) {
        if (t < s) red[t] = fmaxf(red[t], red[t + s]);
        __syncthreads();
    }
    const float mx = red[0];
    __syncthreads();

    float p = expf(e - mx);
    attn[t] = p; red[t] = p;
    __syncthreads();
#pragma unroll
    for (int s = 64; s > 0; s >>= 1) {
        if (t < s) red[t] += red[t + s];
        __syncthreads();
    }
    const float inv_sum = 1.0f / red[0];
    __syncthreads();
    attn[t] *= inv_sum;
    __syncthreads();

    if (t < DH) {
        float r = 0.0f;
#pragma unroll 8
        for (int n = 0; n < NN; n++) r += attn[n] * hs_s[n][t];
        int col = DD + h * DH + t;
        if (mdst) mdst[b * TWO_D + col] = r;
        __half hh = __float2half_rn(r);
        g_m_hi[b * TWO_D + col] = hh;
        g_m_lo[b * TWO_D + col] = __float2half_rn(r - __half2float(hh));
    }
}

// ---------------- launcher ----------------------------------------------------
extern "C" void kernel_launch(void* const* d_in, const int* in_sizes, int n_in,
                              void* d_out, int out_size) {
    const float* X     = (const float*)d_in[0];
    const float* mask  = (const float*)d_in[1];
    const float* fc_w  = (const float*)d_in[2];
    const float* fc_b  = (const float*)d_in[3];
    const float* w_im  = (const float*)d_in[4];
    const float* b_i   = (const float*)d_in[5];
    const float* w_fm  = (const float*)d_in[6];
    const float* b_f   = (const float*)d_in[7];
    const float* w_cm  = (const float*)d_in[8];
    const float* b_c   = (const float*)d_in[9];
    const float* w_om  = (const float*)d_in[10];
    const float* b_o   = (const float*)d_in[11];
    const float* m2q   = (const float*)d_in[12];
    const float* att_v = (const float*)d_in[13];
    float* out = (float*)d_out;

    float *p_hs, *p_query;
    __half *p_x_hi, *p_x_lo, *p_m_hi, *p_m_lo, *p_fc_h, *p_wg_h, *p_q_h;
    cudaGetSymbolAddress((void**)&p_hs,    g_hs);
    cudaGetSymbolAddress((void**)&p_query, g_query);
    cudaGetSymbolAddress((void**)&p_x_hi,  g_x_hi);
    cudaGetSymbolAddress((void**)&p_x_lo,  g_x_lo);
    cudaGetSymbolAddress((void**)&p_m_hi,  g_m_hi);
    cudaGetSymbolAddress((void**)&p_m_lo,  g_m_lo);
    cudaGetSymbolAddress((void**)&p_fc_h,  g_fc_h);
    cudaGetSymbolAddress((void**)&p_wg_h,  g_wg_h);
    cudaGetSymbolAddress((void**)&p_q_h,   g_q_h);

    const int SM_PROJ  = (2 * 128 + 64) * 128 * 2;  // 81920  -> 2 CTAs/SM
    const int SM_GATE  = (2 * 64  + 64) * 128 * 3;  // 73728  -> 2 CTAs/SM
    const int SM_QUERY = (2 * 32  + 64) * 128 * 3;  // 49152  -> 2 CTAs/SM
    cudaFuncSetAttribute((const void*)mma_gemm_kernel<128, 64, 2, 4, false, 2, 2>,
                         cudaFuncAttributeMaxDynamicSharedMemorySize, SM_PROJ);
    cudaFuncSetAttribute((const void*)mma_gemm_kernel<64, 64, 2, 4, true, 2, 3>,
                         cudaFuncAttributeMaxDynamicSharedMemorySize, SM_GATE);
    cudaFuncSetAttribute((const void*)mma_gemm_kernel<32, 64, 2, 4, false, 2, 3>,
                         cudaFuncAttributeMaxDynamicSharedMemorySize, SM_QUERY);

    // my launches 1-3; proj is #4 (ncu slot 6 given 2 harness-prepended launches)
    conv_x_kernel<<<((int)((size_t)BB * NN * DD / 4) + 255) / 256, 256>>>(X);
    dim3 gfc(DD / 32, DD / 32);
    packT_kernel<<<gfc, 256>>>(fc_w, p_fc_h, DD, DD, 1, 0);
    init_step1_kernel<<<1, DD>>>(b_i, b_f, b_c, b_o, m2q);

    // projection GEMM: hs = X @ fc_w + fc_b
    {
        dim3 grid(DD / 64, (BB * NN) / 128);
        mma_gemm_kernel<128, 64, 2, 4, false, 2, 2><<<grid, 256, SM_PROJ>>>(
            DD, p_x_hi, p_x_lo, DD, p_fc_h, DD, p_hs, DD, fc_b,
            nullptr, nullptr, nullptr, nullptr, nullptr);
    }

    bcast_step1_kernel<<<BB, DD>>>();
    packT_kernel<<<gfc, 256>>>(m2q, p_q_h, DD, DD, 1, 0);
    dim3 gg(DD / 32, TWO_D / 32);
    packT_kernel<<<gg, 256>>>(w_im, p_wg_h, TWO_D, DD, 4, 0);
    packT_kernel<<<gg, 256>>>(w_fm, p_wg_h, TWO_D, DD, 4, 1);
    packT_kernel<<<gg, 256>>>(w_cm, p_wg_h, TWO_D, DD, 4, 2);
    packT_kernel<<<gg, 256>>>(w_om, p_wg_h, TWO_D, DD, 4, 3);

    // step 1: attention only (analytic shortcut supplies query/c/m)
    attention_kernel<<<BB * HH, 128>>>(mask, att_v, nullptr);

    // steps 2..6
    for (int step = 0; step < STEPS - 1; step++) {
        const bool last = (step == STEPS - 2);
        {
            dim3 grid((4 * DD) / 64, BB / 64);
            mma_gemm_kernel<64, 64, 2, 4, true, 2, 3><<<grid, 256, SM_GATE>>>(
                TWO_D, p_m_hi, p_m_lo, TWO_D, p_wg_h, TWO_D,
                nullptr, 0, nullptr, b_i, b_f, b_c, b_o, last ? out : nullptr);
        }
        {
            dim3 grid(DD / 64, BB / 32);
            mma_gemm_kernel<32, 64, 2, 4, false, 2, 3><<<grid, 256, SM_QUERY>>>(
                DD, p_m_hi, p_m_lo, TWO_D, p_q_h, DD,
                p_query, DD, nullptr, nullptr, nullptr, nullptr, nullptr, nullptr);
        }
        attention_kernel<<<BB * HH, 128>>>(mask, att_v, last ? out : nullptr);
    }
}